// round 13
// baseline (speedup 1.0000x reference)
#include <cuda_runtime.h>
#include <cuda_bf16.h>
#include <cstdint>

// Problem constants
#define HW_N   262144      // H*W
#define KN     512         // num_embeddings
#define DN     64          // embedding_dim
#define EMA_D  0.99f
#define EPS    1e-5f

// Output layout (reference return order, all fp32):
#define O_ZQ    0               // z_q_st   [H,W,D] 16777216
#define O_IDX   16777216        // indices  [H,W]     262144
#define O_MIND  17039360        // min_dist [N]       262144
#define O_CB    17301504        // new_codebook [K,D]  32768
#define O_CS    17334272        // new_ema_cluster [K]   512
#define O_SUM   17334784        // new_ema_emb_sum [K,D] 32768

__device__ float g_counts[KN];
__device__ float g_sums[KN * DN];
__device__ float g_bsq[KN];

// ---------------------------------------------------------------------------
// m16n8k8 tf32 mma.sync (baseline PTX, works on compute_103 target).
// Operands fed as raw f32 bits -> HW truncates to tf32 (deterministic);
// exact recheck downstream restores reference-exact decisions.
// ---------------------------------------------------------------------------
__device__ __forceinline__ void mma_tf32(float* c, const uint32_t* a,
                                         const uint32_t* b) {
    asm volatile(
        "mma.sync.aligned.m16n8k8.row.col.f32.tf32.tf32.f32 "
        "{%0,%1,%2,%3}, {%4,%5,%6,%7}, {%8,%9}, {%0,%1,%2,%3};"
        : "+f"(c[0]), "+f"(c[1]), "+f"(c[2]), "+f"(c[3])
        : "r"(a[0]), "r"(a[1]), "r"(a[2]), "r"(a[3]), "r"(b[0]), "r"(b[1]));
}

__device__ __forceinline__ void top4_insert(float* v, int* ix, float val, int idx) {
    if (val < v[3] || (val == v[3] && idx < ix[3])) {
        if (val < v[0] || (val == v[0] && idx < ix[0])) {
            v[3]=v[2]; ix[3]=ix[2]; v[2]=v[1]; ix[2]=ix[1];
            v[1]=v[0]; ix[1]=ix[0]; v[0]=val;  ix[0]=idx;
        } else if (val < v[1] || (val == v[1] && idx < ix[1])) {
            v[3]=v[2]; ix[3]=ix[2]; v[2]=v[1]; ix[2]=ix[1];
            v[1]=val;  ix[1]=idx;
        } else if (val < v[2] || (val == v[2] && idx < ix[2])) {
            v[3]=v[2]; ix[3]=ix[2]; v[2]=val; ix[2]=idx;
        } else { v[3]=val; ix[3]=idx; }
    }
}

// ---------------------------------------------------------------------------
// Kernel 1: zero scratch + exact codebook squared norms (sequential order)
// ---------------------------------------------------------------------------
__global__ void vq_init_kernel(const float* __restrict__ cb) {
    int t = blockIdx.x * 128 + threadIdx.x;   // 0..32767
    g_sums[t] = 0.0f;
    if (t < KN) {
        g_counts[t] = 0.0f;
        const float4* row = (const float4*)(cb + t * DN);
        float4 v[16];
#pragma unroll
        for (int i = 0; i < 16; i++) v[i] = row[i];
        float s = 0.0f;
#pragma unroll
        for (int i = 0; i < 16; i++) {
            s = __fadd_rn(s, __fmul_rn(v[i].x, v[i].x));
            s = __fadd_rn(s, __fmul_rn(v[i].y, v[i].y));
            s = __fadd_rn(s, __fmul_rn(v[i].z, v[i].z));
            s = __fadd_rn(s, __fmul_rn(v[i].w, v[i].w));
        }
        g_bsq[t] = s;
    }
}

// ---------------------------------------------------------------------------
// Kernel 2: persistent tf32 mma.sync distance GEMM + top-4 + exact recheck
//   grid=148 x 256 threads (8 warps). Codebook resident in smem.
//   Per warp: 32 points, A-frags for K=64 in regs, N in 16 chunks of 32.
// ---------------------------------------------------------------------------
#define ZS    68
#define NPB   256
#define TILES (HW_N / NPB)    // 1024
#define GRID  148
// smem: zlin 256*68 | cbs 512*68 | bsq 512 | cand 256*4(int)
#define SM_FLOATS (NPB*ZS + KN*ZS + KN + NPB*4)
#define SM_BYTES  (SM_FLOATS * 4)   // 215040

__global__ __launch_bounds__(256, 1)
void vq_main_kernel(const float* __restrict__ z_e,
                    const float* __restrict__ cbook,
                    float* __restrict__ out) {
    extern __shared__ float sm[];
    float* zlin = sm;                    // [256][68]
    float* cbs  = zlin + NPB * ZS;       // [512][68]
    float* bsq  = cbs + KN * ZS;         // [512]
    int*   cand = (int*)(bsq + KN);      // [256][4]

    const int tid  = threadIdx.x;
    const int lane = tid & 31;
    const int warp = tid >> 5;
    const int g    = lane >> 2;   // group (0..7)
    const int tg   = lane & 3;    // thread-in-group

    // ---- codebook -> smem once (row-major, pitch 68; conflict-free frags)
    for (int i = tid; i < KN * DN / 4; i += 256) {
        int row = i >> 4, c4 = i & 15;
        float4 v = *(const float4*)(cbook + (size_t)row * DN + c4 * 4);
        *(float4*)&cbs[row * ZS + c4 * 4] = v;
    }
    for (int i = tid; i < KN; i += 256) bsq[i] = g_bsq[i];
    __syncthreads();

    for (int tile = blockIdx.x; tile < TILES; tile += GRID) {
        const int pbase = tile * NPB;

        // ---- z tile -> smem (4096 float4 slots)
#pragma unroll
        for (int i = 0; i < 16; i++) {
            int e = tid + i * 256;
            int row = e >> 4, c4 = e & 15;
            float4 v = *(const float4*)(z_e + (size_t)(pbase + row) * DN + c4 * 4);
            *(float4*)&zlin[row * ZS + c4 * 4] = v;
        }
        __syncthreads();

        // ---- a_sq for own point (exact sequential)
        float asq = 0.0f;
#pragma unroll
        for (int d = 0; d < DN; d++) {
            float v = zlin[tid * ZS + d];
            asq = __fadd_rn(asq, __fmul_rn(v, v));
        }

        // ---- A fragments for this warp's 32 rows, all K (held in regs)
        uint32_t afr[2][8][4];
        const int bm = warp * 32;
#pragma unroll
        for (int t = 0; t < 2; t++)
#pragma unroll
            for (int s = 0; s < 8; s++) {
                int r0 = bm + t * 16 + g, r1 = r0 + 8;
                int k0 = s * 8 + tg;
                afr[t][s][0] = __float_as_uint(zlin[r0 * ZS + k0]);
                afr[t][s][1] = __float_as_uint(zlin[r1 * ZS + k0]);
                afr[t][s][2] = __float_as_uint(zlin[r0 * ZS + k0 + 4]);
                afr[t][s][3] = __float_as_uint(zlin[r1 * ZS + k0 + 4]);
            }

        // ---- top-4 per row; rows handled: bm + g + 8q, q=0..3
        float tv[4][4]; int ti[4][4];
#pragma unroll
        for (int q = 0; q < 4; q++)
#pragma unroll
            for (int j = 0; j < 4; j++) { tv[q][j] = 3.4e38f; ti[q][j] = KN; }

        for (int chunk = 0; chunk < 16; chunk++) {
            float acc[2][4][4];
#pragma unroll
            for (int t = 0; t < 2; t++)
#pragma unroll
                for (int u = 0; u < 4; u++)
#pragma unroll
                    for (int j = 0; j < 4; j++) acc[t][u][j] = 0.0f;

#pragma unroll
            for (int s = 0; s < 8; s++) {
                uint32_t bfr[4][2];
#pragma unroll
                for (int u = 0; u < 4; u++) {
                    int n  = chunk * 32 + u * 8 + g;
                    int k0 = s * 8 + tg;
                    bfr[u][0] = __float_as_uint(cbs[n * ZS + k0]);
                    bfr[u][1] = __float_as_uint(cbs[n * ZS + k0 + 4]);
                }
#pragma unroll
                for (int t = 0; t < 2; t++)
#pragma unroll
                    for (int u = 0; u < 4; u++)
                        mma_tf32(acc[t][u], afr[t][s], bfr[u]);
            }

            // vals + top-4 (codes ascending within thread; lex insert)
#pragma unroll
            for (int u = 0; u < 4; u++) {
                int c0 = chunk * 32 + u * 8 + tg * 2;
                float2 bb = *(const float2*)&bsq[c0];
#pragma unroll
                for (int t = 0; t < 2; t++) {
                    top4_insert(tv[2*t],   ti[2*t],   fmaf(-2.0f, acc[t][u][0], bb.x), c0);
                    top4_insert(tv[2*t],   ti[2*t],   fmaf(-2.0f, acc[t][u][1], bb.y), c0 + 1);
                    top4_insert(tv[2*t+1], ti[2*t+1], fmaf(-2.0f, acc[t][u][2], bb.x), c0);
                    top4_insert(tv[2*t+1], ti[2*t+1], fmaf(-2.0f, acc[t][u][3], bb.y), c0 + 1);
                }
            }
        }

        // ---- merge top-4 across the 4 lanes sharing each row (xor 1, 2)
#pragma unroll
        for (int off = 1; off <= 2; off <<= 1) {
#pragma unroll
            for (int q = 0; q < 4; q++) {
                float ov[4]; int oi[4];
#pragma unroll
                for (int j = 0; j < 4; j++) {
                    ov[j] = __shfl_xor_sync(0xFFFFFFFFu, tv[q][j], off);
                    oi[j] = __shfl_xor_sync(0xFFFFFFFFu, ti[q][j], off);
                }
#pragma unroll
                for (int j = 0; j < 4; j++)
                    top4_insert(tv[q], ti[q], ov[j], oi[j]);
            }
        }
        if (tg == 0) {
#pragma unroll
            for (int q = 0; q < 4; q++) {
                int p = bm + g + 8 * q;
#pragma unroll
                for (int j = 0; j < 4; j++) cand[p * 4 + j] = ti[q][j];
            }
        }
        __syncthreads();

        // ---- exact recheck of 4 finalists (validated arithmetic):
        //   dot = sequential-k single-accumulator fmaf
        //   val = rn(rn(asq - rn(2*dot)) + bsq), ties -> lowest index
        {
            int   ci[4];
            float ev[4];
#pragma unroll
            for (int j = 0; j < 4; j++) ci[j] = cand[tid * 4 + j];
#pragma unroll
            for (int j = 0; j < 4; j++) {
                const float* crow = &cbs[ci[j] * ZS];
                float dv = 0.0f;
#pragma unroll
                for (int d = 0; d < DN; d++)
                    dv = fmaf(zlin[tid * ZS + d], crow[d], dv);
                ev[j] = __fadd_rn(__fsub_rn(asq, __fmul_rn(2.0f, dv)), bsq[ci[j]]);
            }
            int wi = ci[0]; float wv = ev[0];
#pragma unroll
            for (int j = 1; j < 4; j++)
                if (ev[j] < wv || (ev[j] == wv && ci[j] < wi)) { wv = ev[j]; wi = ci[j]; }

            out[O_IDX  + pbase + tid] = (float)wi;
            out[O_MIND + pbase + tid] = wv;
            atomicAdd(&g_counts[wi], 1.0f);

            // ---- epilogue: z_q_st + EMA embedding scatter
            float* orow = out + O_ZQ + (size_t)(pbase + tid) * DN;
            float* srow = g_sums + (size_t)wi * DN;
            const float* crow = &cbs[wi * ZS];
#pragma unroll
            for (int q = 0; q < 16; q++) {
                int d = q * 4;
                float4 z = *(const float4*)&zlin[tid * ZS + d];
                float4 c = *(const float4*)(crow + d);
                float4 rr;
                rr.x = __fadd_rn(z.x, __fsub_rn(c.x, z.x));
                rr.y = __fadd_rn(z.y, __fsub_rn(c.y, z.y));
                rr.z = __fadd_rn(z.z, __fsub_rn(c.z, z.z));
                rr.w = __fadd_rn(z.w, __fsub_rn(c.w, z.w));
                *(float4*)(orow + d) = rr;
                asm volatile("red.global.add.v4.f32 [%0], {%1, %2, %3, %4};"
                             :: "l"(srow + d), "f"(z.x), "f"(z.y), "f"(z.z), "f"(z.w)
                             : "memory");
            }
        }
        __syncthreads();   // zlin/cand reuse safe for next tile
    }
}

// ---------------------------------------------------------------------------
// Kernel 3: EMA update + new codebook (exact rn ops)
// ---------------------------------------------------------------------------
__global__ void vq_final_kernel(const float* __restrict__ ema_cs,
                                const float* __restrict__ ema_sum,
                                float* __restrict__ out) {
    int k = blockIdx.x;
    int d = threadIdx.x;
    float cs_new = __fadd_rn(__fmul_rn(EMA_D, ema_cs[k]),
                             __fmul_rn(1.0f - EMA_D, g_counts[k]));
    if (d == 0) out[O_CS + k] = cs_new;
    float s_new = __fadd_rn(__fmul_rn(EMA_D, ema_sum[k * DN + d]),
                            __fmul_rn(1.0f - EMA_D, g_sums[k * DN + d]));
    out[O_SUM + k * DN + d] = s_new;
    out[O_CB  + k * DN + d] = __fdiv_rn(s_new, __fadd_rn(cs_new, EPS));
}

// ---------------------------------------------------------------------------
extern "C" void kernel_launch(void* const* d_in, const int* in_sizes, int n_in,
                              void* d_out, int out_size) {
    const float* z_e      = (const float*)d_in[0];
    const float* codebook = (const float*)d_in[1];
    const float* ema_cs   = (const float*)d_in[2];
    const float* ema_sum  = (const float*)d_in[3];
    float* out = (float*)d_out;

    cudaFuncSetAttribute(vq_main_kernel,
                         cudaFuncAttributeMaxDynamicSharedMemorySize, SM_BYTES);

    vq_init_kernel<<<256, 128>>>(codebook);
    vq_main_kernel<<<GRID, 256, SM_BYTES>>>(z_e, codebook, out);
    vq_final_kernel<<<KN, DN>>>(ema_cs, ema_sum, out);
}